// round 9
// baseline (speedup 1.0000x reference)
#include <cuda_runtime.h>
#include <cuda_bf16.h>
#include <math.h>
#include <cstdint>

#define T_  512
#define B_  256
#define D_  512
#define H_  512
#define H2_ (2*H_)
#define H3_ (3*H_)

#define NBLK  128
#define SNTHR 512

typedef unsigned long long ull;

// ===========================================================================
// Global scratch
// ===========================================================================
__device__ float g_gi[(size_t)T_ * B_ * H3_];          // gi = ins @ Wi + bi
__device__ float g_mask[T_ * B_];
__device__ __nv_bfloat16 g_ah[(size_t)T_ * B_ * D_];   // ins hi
__device__ __nv_bfloat16 g_al[(size_t)T_ * B_ * D_];   // ins lo
__device__ __nv_bfloat16 g_bh[(size_t)H3_ * D_];       // Wi^T hi  [n][k]
__device__ __nv_bfloat16 g_bl[(size_t)H3_ * D_];       // Wi^T lo
__device__ unsigned g_cnt8[8 * 32];
__device__ volatile unsigned g_gen8[8 * 32];

// ===========================================================================
// helpers
// ===========================================================================
__device__ __forceinline__ uint32_t smem_u32(const void* p) {
    uint32_t a;
    asm("{ .reg .u64 t; cvta.to.shared.u64 t, %1; cvt.u32.u64 %0, t; }"
        : "=r"(a) : "l"(p));
    return a;
}

#define LDSM4(R, A) \
    asm volatile("ldmatrix.sync.aligned.m8n8.x4.shared.b16 {%0,%1,%2,%3}, [%4];" \
        : "=r"((R)[0]), "=r"((R)[1]), "=r"((R)[2]), "=r"((R)[3]) : "r"(A))
#define LDSM2(R, A) \
    asm volatile("ldmatrix.sync.aligned.m8n8.x2.shared.b16 {%0,%1}, [%2];" \
        : "=r"((R)[0]), "=r"((R)[1]) : "r"(A))

__device__ __forceinline__ void mma4(float* c, const unsigned* a,
                                     unsigned b0, unsigned b1) {
    asm volatile(
        "mma.sync.aligned.m16n8k16.row.col.f32.bf16.bf16.f32 "
        "{%0,%1,%2,%3}, {%4,%5,%6,%7}, {%8,%9}, {%0,%1,%2,%3};"
        : "+f"(c[0]), "+f"(c[1]), "+f"(c[2]), "+f"(c[3])
        : "r"(a[0]), "r"(a[1]), "r"(a[2]), "r"(a[3]), "r"(b0), "r"(b1));
}

__device__ __forceinline__ void split_f4(float4 v, ull& hi, ull& lo) {
    __nv_bfloat16 h0 = __float2bfloat16(v.x);
    __nv_bfloat16 h1 = __float2bfloat16(v.y);
    __nv_bfloat16 h2 = __float2bfloat16(v.z);
    __nv_bfloat16 h3 = __float2bfloat16(v.w);
    __nv_bfloat16 l0 = __float2bfloat16(v.x - __bfloat162float(h0));
    __nv_bfloat16 l1 = __float2bfloat16(v.y - __bfloat162float(h1));
    __nv_bfloat16 l2 = __float2bfloat16(v.z - __bfloat162float(h2));
    __nv_bfloat16 l3 = __float2bfloat16(v.w - __bfloat162float(h3));
    unsigned short hu[4] = { *(unsigned short*)&h0, *(unsigned short*)&h1,
                             *(unsigned short*)&h2, *(unsigned short*)&h3 };
    unsigned short lu[4] = { *(unsigned short*)&l0, *(unsigned short*)&l1,
                             *(unsigned short*)&l2, *(unsigned short*)&l3 };
    hi = *(ull*)hu; lo = *(ull*)lu;
}

__device__ __forceinline__ void split_f1(float v, unsigned short& hi,
                                         unsigned short& lo) {
    __nv_bfloat16 h = __float2bfloat16(v);
    __nv_bfloat16 l = __float2bfloat16(v - __bfloat162float(h));
    hi = *(unsigned short*)&h;
    lo = *(unsigned short*)&l;
}

// ===========================================================================
// Reset-mask prep
// ===========================================================================
__global__ void prep_mask_kernel(const void* __restrict__ resets)
{
    const int N = T_ * B_;
    const unsigned char* b8 = (const unsigned char*)resets;
    int found = 0;
    for (int i = threadIdx.x; i < N; i += blockDim.x)
        if ((i & 3) && b8[i] == 1) found = 1;
    int is_byte = __syncthreads_or(found);
    if (is_byte) {
        for (int i = threadIdx.x; i < N; i += blockDim.x)
            g_mask[i] = b8[i] ? 0.0f : 1.0f;
    } else {
        const unsigned int* w32 = (const unsigned int*)resets;
        for (int i = threadIdx.x; i < N; i += blockDim.x)
            g_mask[i] = w32[i] ? 0.0f : 1.0f;
    }
}

// ===========================================================================
// Split conversion for A (ins) and B (Wi^T) in ONE kernel
// ===========================================================================
__global__ void conv_ab_kernel(const float* __restrict__ ins,
                               const float* __restrict__ Wi)
{
    const size_t totalA = (size_t)T_ * B_ * D_ / 8;
    const size_t totalB = (size_t)H3_ * (D_ / 8);
    const size_t total = totalA + totalB;
    for (size_t i = (size_t)blockIdx.x * blockDim.x + threadIdx.x;
         i < total; i += (size_t)gridDim.x * blockDim.x) {
        if (i < totalA) {
            size_t base = i * 8;
            float4 a = *(const float4*)(ins + base);
            float4 b = *(const float4*)(ins + base + 4);
            ull h0, l0, h1, l1;
            split_f4(a, h0, l0); split_f4(b, h1, l1);
            *(ull*)&g_ah[base] = h0; *(ull*)&g_ah[base + 4] = h1;
            *(ull*)&g_al[base] = l0; *(ull*)&g_al[base + 4] = l1;
        } else {
            size_t j = i - totalA;
            int n = (int)(j % H3_);
            int k8 = (int)(j / H3_) * 8;
            float4 a, b;
            a.x = Wi[(size_t)(k8+0)*H3_ + n]; a.y = Wi[(size_t)(k8+1)*H3_ + n];
            a.z = Wi[(size_t)(k8+2)*H3_ + n]; a.w = Wi[(size_t)(k8+3)*H3_ + n];
            b.x = Wi[(size_t)(k8+4)*H3_ + n]; b.y = Wi[(size_t)(k8+5)*H3_ + n];
            b.z = Wi[(size_t)(k8+6)*H3_ + n]; b.w = Wi[(size_t)(k8+7)*H3_ + n];
            ull h0, l0, h1, l1;
            split_f4(a, h0, l0); split_f4(b, h1, l1);
            size_t o = (size_t)n * D_ + k8;
            *(ull*)&g_bh[o] = h0; *(ull*)&g_bh[o + 4] = h1;
            *(ull*)&g_bl[o] = l0; *(ull*)&g_bl[o + 4] = l1;
        }
    }
}

// ===========================================================================
// gi GEMM (unchanged from R8 — measured tensor=50%)
// ===========================================================================
#define SAK 40

__global__ __launch_bounds__(256)
void gi_gemm_kernel(const float* __restrict__ bias, float* __restrict__ C)
{
    __shared__ __nv_bfloat16 sAh[128 * SAK], sAl[128 * SAK];
    __shared__ __nv_bfloat16 sBh[128 * SAK], sBl[128 * SAK];

    const int tid = threadIdx.x;
    const int n0  = blockIdx.x * 128;
    const int m0  = blockIdx.y * 128;
    const int wid = tid >> 5, lane = tid & 31;
    const int wm = (wid & 1) * 64;
    const int wn = (wid >> 1) * 32;
    const int g  = lane >> 2;
    const int tg = lane & 3;

    const int sr = tid >> 1, sk = (tid & 1) * 16;
    const __nv_bfloat16* pAh = g_ah + (size_t)(m0 + sr) * D_ + sk;
    const __nv_bfloat16* pAl = g_al + (size_t)(m0 + sr) * D_ + sk;
    const __nv_bfloat16* pBh = g_bh + (size_t)(n0 + sr) * D_ + sk;
    const __nv_bfloat16* pBl = g_bl + (size_t)(n0 + sr) * D_ + sk;

    const uint32_t aH = smem_u32(sAh) + (((wm + (lane & 15)) * SAK) +
                        ((lane & 16) ? 8 : 0)) * 2;
    const uint32_t aL = aH + (uint32_t)(sAl - sAh) * 2;
    const uint32_t bH = smem_u32(sBh) + (((wn + (lane & 7) +
                        ((lane & 16) ? 8 : 0)) * SAK) +
                        ((lane & 8) ? 8 : 0)) * 2;
    const uint32_t bL = bH + (uint32_t)(sBl - sBh) * 2;
    const int mstep = 16 * SAK * 2;
    const int nstep = 16 * SAK * 2;

    float acc[4][4][4];
    #pragma unroll
    for (int i = 0; i < 4; i++)
        #pragma unroll
        for (int j = 0; j < 4; j++)
            #pragma unroll
            for (int q = 0; q < 4; q++) acc[i][j][q] = 0.0f;

    uint4 rah0, rah1, ral0, ral1, rbh0, rbh1, rbl0, rbl1;
    rah0 = *(const uint4*)(pAh);     rah1 = *(const uint4*)(pAh + 8);
    ral0 = *(const uint4*)(pAl);     ral1 = *(const uint4*)(pAl + 8);
    rbh0 = *(const uint4*)(pBh);     rbh1 = *(const uint4*)(pBh + 8);
    rbl0 = *(const uint4*)(pBl);     rbl1 = *(const uint4*)(pBl + 8);

    for (int kc = 0; kc < D_ / 32; kc++) {
        __syncthreads();
        *(uint4*)&sAh[sr * SAK + sk] = rah0;  *(uint4*)&sAh[sr * SAK + sk + 8] = rah1;
        *(uint4*)&sAl[sr * SAK + sk] = ral0;  *(uint4*)&sAl[sr * SAK + sk + 8] = ral1;
        *(uint4*)&sBh[sr * SAK + sk] = rbh0;  *(uint4*)&sBh[sr * SAK + sk + 8] = rbh1;
        *(uint4*)&sBl[sr * SAK + sk] = rbl0;  *(uint4*)&sBl[sr * SAK + sk + 8] = rbl1;
        __syncthreads();

        if (kc + 1 < D_ / 32) {
            int k0 = (kc + 1) * 32;
            rah0 = *(const uint4*)(pAh + k0);  rah1 = *(const uint4*)(pAh + k0 + 8);
            ral0 = *(const uint4*)(pAl + k0);  ral1 = *(const uint4*)(pAl + k0 + 8);
            rbh0 = *(const uint4*)(pBh + k0);  rbh1 = *(const uint4*)(pBh + k0 + 8);
            rbl0 = *(const uint4*)(pBl + k0);  rbl1 = *(const uint4*)(pBl + k0 + 8);
        }

        #pragma unroll
        for (int ks = 0; ks < 2; ks++) {
            const int k2 = ks * 32;
            unsigned bh01[4], bh23[4], bl01[4], bl23[4];
            LDSM4(bh01, bH + k2);
            LDSM4(bh23, bH + nstep + k2);
            LDSM4(bl01, bL + k2);
            LDSM4(bl23, bL + nstep + k2);
            #pragma unroll
            for (int mi = 0; mi < 4; mi++) {
                unsigned ah[4], al[4];
                LDSM4(ah, aH + mi * mstep + k2);
                LDSM4(al, aL + mi * mstep + k2);
                mma4(acc[mi][0], ah, bh01[0], bh01[1]);
                mma4(acc[mi][1], ah, bh01[2], bh01[3]);
                mma4(acc[mi][2], ah, bh23[0], bh23[1]);
                mma4(acc[mi][3], ah, bh23[2], bh23[3]);
                mma4(acc[mi][0], al, bh01[0], bh01[1]);
                mma4(acc[mi][1], al, bh01[2], bh01[3]);
                mma4(acc[mi][2], al, bh23[0], bh23[1]);
                mma4(acc[mi][3], al, bh23[2], bh23[3]);
                mma4(acc[mi][0], ah, bl01[0], bl01[1]);
                mma4(acc[mi][1], ah, bl01[2], bl01[3]);
                mma4(acc[mi][2], ah, bl23[0], bl23[1]);
                mma4(acc[mi][3], ah, bl23[2], bl23[3]);
            }
        }
    }

    #pragma unroll
    for (int ni = 0; ni < 4; ni++) {
        int col = n0 + wn + ni * 8 + tg * 2;
        float b0 = bias[col], b1 = bias[col + 1];
        #pragma unroll
        for (int mi = 0; mi < 4; mi++) {
            int row = m0 + wm + mi * 16 + g;
            float2 o0 = make_float2(acc[mi][ni][0] + b0, acc[mi][ni][1] + b1);
            float2 o1 = make_float2(acc[mi][ni][2] + b0, acc[mi][ni][3] + b1);
            *(float2*)(C + (size_t)row * H3_ + col) = o0;
            *(float2*)(C + (size_t)(row + 8) * H3_ + col) = o1;
        }
    }
}

// ===========================================================================
// Per-batch-group barrier (16 blocks / batch tile)
// ===========================================================================
__device__ __forceinline__ void group_sync(int grp)
{
    __syncthreads();
    if (threadIdx.x == 0) {
        unsigned g = g_gen8[grp * 32];
        __threadfence();
        if (atomicAdd(&g_cnt8[grp * 32], 1) == 15) {
            g_cnt8[grp * 32] = 0;
            __threadfence();
            g_gen8[grp * 32] = g + 1;
        } else {
            while (g_gen8[grp * 32] == g) { __nanosleep(32); }
        }
        __threadfence();
    }
    __syncthreads();
}

// ===========================================================================
// Persistent GRU scan v5: 512 threads, 16 warps = 2m x 4n x 2k-split.
// W resident bf16 hi/lo [96][520]; 2 h chunk buffers (one per k-half);
// smem k-reduction; epilogue across all 512 threads.
// ===========================================================================
#define WKS  520
#define HKS  72
#define OFF_WLO  99840                  // 96*520*2
#define OFF_HS   199680                 // 2*OFF_WLO
#define HSBUF    9216                   // per half: hi 4608B + lo 4608B
#define GOUT_STR 100
#define OFF_GOUT OFF_HS                 // aliases hs (post-compute)
#define OFF_GRED (OFF_HS + 12800)
#define SCAN_SMEM (OFF_HS + 25600)      // 225280 bytes

__global__ __launch_bounds__(SNTHR, 1)
void gru_scan_kernel(const float* __restrict__ rnn_state,
                     const float* __restrict__ Whrz,
                     const float* __restrict__ Whn,
                     const float* __restrict__ bhn,
                     const float* __restrict__ gi,
                     float* __restrict__ ys)
{
    extern __shared__ char smraw[];
    __nv_bfloat16* Whi = (__nv_bfloat16*)smraw;
    __nv_bfloat16* Wlo = (__nv_bfloat16*)(smraw + OFF_WLO);
    float* gout = (float*)(smraw + OFF_GOUT);
    float* gred = (float*)(smraw + OFF_GRED);

    const int tid = threadIdx.x;
    const int bid = blockIdx.x;
    const int hti = bid & 15, bti = bid >> 4;
    const int hb  = hti * 32;
    const int b0  = bti * 32;

    const int wid = tid >> 5, lane = tid & 31;
    const int wm  = (wid & 1) * 16;          // m offset
    const int wn  = ((wid >> 1) & 3) * 24;   // n offset
    const int kh  = wid >> 3;                // k half
    const int g   = lane >> 2;
    const int tg  = lane & 3;

    // conversion slot (one per half-buffer per thread)
    const int crow = tid >> 4;               // 0..31
    const int ckq  = (tid & 15) * 4;

    // epilogue mapping: float2 per thread over 32b x 32h
    const int eb  = tid >> 4;
    const int eh2 = (tid & 15) * 2;

    const uint32_t smb = smem_u32(smraw);

    // ldmatrix lane bases
    const uint32_t wH01 = smb + (((wn + (lane & 7) + ((lane & 16) ? 8 : 0)) * WKS)
                          + ((lane & 8) ? 8 : 0)) * 2;
    const uint32_t wH2  = smb + (((wn + 16 + (lane & 7)) * WKS)
                          + ((lane & 8) ? 8 : 0)) * 2;
    const uint32_t wL01 = wH01 + OFF_WLO;
    const uint32_t wL2  = wH2 + OFF_WLO;
    const uint32_t hA0  = smb + OFF_HS + kh * HSBUF +
                          (((wm + (lane & 15)) * HKS) + ((lane & 16) ? 8 : 0)) * 2;

    // ---- one-time: W slice -> bf16 hi/lo resident [96][WKS]
    for (int i = tid; i < 96 * 128; i += SNTHR) {
        int n = i >> 7, kq = (i & 127) * 4;
        int gate = n >> 5, hcol = hb + (n & 31);
        const float* src;
        int stride;
        if (gate == 0)      { src = Whrz + hcol;      stride = H2_; }
        else if (gate == 1) { src = Whrz + H_ + hcol; stride = H2_; }
        else                { src = Whn + hcol;       stride = H_;  }
        unsigned short hv[4], lv[4];
        #pragma unroll
        for (int j = 0; j < 4; j++)
            split_f1(src[(size_t)(kq + j) * stride], hv[j], lv[j]);
        *(ull*)&Whi[n * WKS + kq] = *(ull*)hv;
        *(ull*)&Wlo[n * WKS + kq] = *(ull*)lv;
    }

    const float2 bh2 = *(const float2*)(bhn + hb + eh2);
    __syncthreads();

    for (int t = 0; t < T_; t++) {
        const float* hin = (t == 0) ? rnn_state : (ys + (size_t)(t - 1) * B_ * H_);

        const float mc = __ldg(&g_mask[t * B_ + b0 + crow]);
        const float me = __ldg(&g_mask[t * B_ + b0 + eb]);

        // epilogue prefetch (float2 per thread)
        const float* gib = gi + ((size_t)t * B_ + b0 + eb) * H3_ + hb + eh2;
        float2 ir2 = __ldcg((const float2*)(gib));
        float2 iz2 = __ldcg((const float2*)(gib + H_));
        float2 in2 = __ldcg((const float2*)(gib + 2 * H_));
        float2 ho2 = __ldcg((const float2*)(hin + (size_t)(b0 + eb) * H_ + hb + eh2));

        // h chunk pointers: half A = k[0,256), half B = k[256,512)
        const float* hrA = hin + (size_t)(b0 + crow) * H_ + ckq;
        const float* hrB = hrA + 256;
        float4 vA = __ldcg((const float4*)hrA);
        float4 vB = __ldcg((const float4*)hrB);

        float acc[3][4];
        #pragma unroll
        for (int ni = 0; ni < 3; ni++)
            #pragma unroll
            for (int q = 0; q < 4; q++) acc[ni][q] = 0.0f;

        for (int c = 0; c < 4; c++) {
            // convert both halves' chunk c
            {
                __nv_bfloat16* hsA = (__nv_bfloat16*)(smraw + OFF_HS);
                __nv_bfloat16* hsB = (__nv_bfloat16*)(smraw + OFF_HS + HSBUF);
                ull hi, lo;
                split_f4(make_float4(vA.x*mc, vA.y*mc, vA.z*mc, vA.w*mc), hi, lo);
                *(ull*)&hsA[crow * HKS + ckq] = hi;
                *(ull*)&hsA[2304 + crow * HKS + ckq] = lo;
                split_f4(make_float4(vB.x*mc, vB.y*mc, vB.z*mc, vB.w*mc), hi, lo);
                *(ull*)&hsB[crow * HKS + ckq] = hi;
                *(ull*)&hsB[2304 + crow * HKS + ckq] = lo;
            }
            __syncthreads();

            if (c < 3) {
                int off = (c + 1) * 64;
                vA = __ldcg((const float4*)(hrA + off));
                vB = __ldcg((const float4*)(hrB + off));
            }

            #pragma unroll
            for (int ks = 0; ks < 4; ks++) {
                const int kw2 = (kh * 256 + c * 64 + ks * 16) * 2;
                const int kl2 = ks * 32;
                unsigned wh01[4], wh2[2], wl01[4], wl2[2];
                LDSM4(wh01, wH01 + kw2);
                LDSM2(wh2,  wH2 + kw2);
                LDSM4(wl01, wL01 + kw2);
                LDSM2(wl2,  wL2 + kw2);
                unsigned ah[4], al[4];
                LDSM4(ah, hA0 + kl2);
                LDSM4(al, hA0 + 4608 + kl2);
                mma4(acc[0], ah, wh01[0], wh01[1]);
                mma4(acc[1], ah, wh01[2], wh01[3]);
                mma4(acc[2], ah, wh2[0], wh2[1]);
                mma4(acc[0], al, wh01[0], wh01[1]);
                mma4(acc[1], al, wh01[2], wh01[3]);
                mma4(acc[2], al, wh2[0], wh2[1]);
                mma4(acc[0], ah, wl01[0], wl01[1]);
                mma4(acc[1], ah, wl01[2], wl01[3]);
                mma4(acc[2], ah, wl2[0], wl2[1]);
            }
            __syncthreads();
        }

        // ---- k-reduction: kh=1 partials -> gred, kh=0 adds
        if (kh == 1) {
            #pragma unroll
            for (int ni = 0; ni < 3; ni++) {
                int col = wn + ni * 8 + tg * 2;
                *(float2*)&gred[(wm + g) * GOUT_STR + col] =
                    make_float2(acc[ni][0], acc[ni][1]);
                *(float2*)&gred[(wm + g + 8) * GOUT_STR + col] =
                    make_float2(acc[ni][2], acc[ni][3]);
            }
        }
        __syncthreads();
        if (kh == 0) {
            #pragma unroll
            for (int ni = 0; ni < 3; ni++) {
                int col = wn + ni * 8 + tg * 2;
                float2 p0 = *(const float2*)&gred[(wm + g) * GOUT_STR + col];
                float2 p1 = *(const float2*)&gred[(wm + g + 8) * GOUT_STR + col];
                *(float2*)&gout[(wm + g) * GOUT_STR + col] =
                    make_float2(acc[ni][0] + p0.x, acc[ni][1] + p0.y);
                *(float2*)&gout[(wm + g + 8) * GOUT_STR + col] =
                    make_float2(acc[ni][2] + p1.x, acc[ni][3] + p1.y);
            }
        }
        __syncthreads();

        // ---- fused gates (all 512 threads, float2 each)
        {
            float2 cr = *(const float2*)&gout[eb * GOUT_STR + eh2];
            float2 cz = *(const float2*)&gout[eb * GOUT_STR + 32 + eh2];
            float2 cn = *(const float2*)&gout[eb * GOUT_STR + 64 + eh2];

            float hm0 = ho2.x * me, hm1 = ho2.y * me;
            float r0 = 1.0f / (1.0f + __expf(-(ir2.x + cr.x)));
            float r1 = 1.0f / (1.0f + __expf(-(ir2.y + cr.y)));
            float z0 = 1.0f / (1.0f + __expf(-(iz2.x + cz.x)));
            float z1 = 1.0f / (1.0f + __expf(-(iz2.y + cz.y)));
            float e0 = __expf(2.0f * (in2.x + r0 * (cn.x + bh2.x)));
            float e1 = __expf(2.0f * (in2.y + r1 * (cn.y + bh2.y)));
            float n0 = __fdividef(e0 - 1.0f, e0 + 1.0f);
            float n1 = __fdividef(e1 - 1.0f, e1 + 1.0f);

            float2 out;
            out.x = (1.0f - z0) * n0 + z0 * hm0;
            out.y = (1.0f - z1) * n1 + z1 * hm1;
            *(float2*)(ys + ((size_t)t * B_ + b0 + eb) * H_ + hb + eh2) = out;
        }

        group_sync(bti);
    }
}

// ===========================================================================
extern "C" void kernel_launch(void* const* d_in, const int* in_sizes, int n_in,
                              void* d_out, int out_size)
{
    const float* rnn_state = (const float*)d_in[0];
    const float* ins       = (const float*)d_in[1];
    const void*  resets    = d_in[2];
    const float* Wi        = (const float*)d_in[3];
    const float* bi        = (const float*)d_in[4];
    const float* Whrz      = (const float*)d_in[5];
    const float* Whn       = (const float*)d_in[6];
    const float* bhn       = (const float*)d_in[7];

    float* final_h = (float*)d_out;
    float* ys      = (float*)d_out + (size_t)B_ * H_;

    float* gi_ptr = nullptr;
    cudaGetSymbolAddress((void**)&gi_ptr, g_gi);

    cudaFuncSetAttribute(gru_scan_kernel,
                         cudaFuncAttributeMaxDynamicSharedMemorySize, SCAN_SMEM);

    prep_mask_kernel<<<1, 1024>>>(resets);               // launch #3
    conv_ab_kernel<<<2048, 256>>>(ins, Wi);              // launch #4
    gi_gemm_kernel<<<dim3(H3_ / 128, (T_ * B_) / 128), 256>>>(bi, gi_ptr);  // #5
    gru_scan_kernel<<<NBLK, SNTHR, SCAN_SMEM>>>(rnn_state, Whrz, Whn, bhn,
                                                gi_ptr, ys);                // #6
    cudaMemcpyAsync(final_h, ys + (size_t)(T_ - 1) * B_ * H_,
                    (size_t)B_ * H_ * sizeof(float),
                    cudaMemcpyDeviceToDevice, 0);
}

// round 10
// speedup vs baseline: 1.5741x; 1.5741x over previous
#include <cuda_runtime.h>
#include <cuda_fp16.h>
#include <math.h>
#include <cstdint>

#define T_  512
#define B_  256
#define D_  512
#define H_  512
#define H2_ (2*H_)
#define H3_ (3*H_)

#define NBLK  128
#define SNTHR 512

typedef unsigned long long ull;

// ===========================================================================
// Global scratch
// ===========================================================================
__device__ float g_gi[(size_t)T_ * B_ * H3_];          // gi = ins @ Wi + bi
__device__ float g_mask[T_ * B_];
__device__ __half g_ah[(size_t)T_ * B_ * D_];          // ins fp16 [m][k]
__device__ __half g_bh[(size_t)H3_ * D_];              // Wi^T fp16 [n][k]
__device__ unsigned g_cnt8[8 * 32];
__device__ volatile unsigned g_gen8[8 * 32];

// ===========================================================================
// helpers
// ===========================================================================
__device__ __forceinline__ uint32_t smem_u32(const void* p) {
    uint32_t a;
    asm("{ .reg .u64 t; cvta.to.shared.u64 t, %1; cvt.u32.u64 %0, t; }"
        : "=r"(a) : "l"(p));
    return a;
}

#define LDSM4(R, A) \
    asm volatile("ldmatrix.sync.aligned.m8n8.x4.shared.b16 {%0,%1,%2,%3}, [%4];" \
        : "=r"((R)[0]), "=r"((R)[1]), "=r"((R)[2]), "=r"((R)[3]) : "r"(A))
#define LDSM2(R, A) \
    asm volatile("ldmatrix.sync.aligned.m8n8.x2.shared.b16 {%0,%1}, [%2];" \
        : "=r"((R)[0]), "=r"((R)[1]) : "r"(A))

__device__ __forceinline__ void mma4(float* c, const unsigned* a,
                                     unsigned b0, unsigned b1) {
    asm volatile(
        "mma.sync.aligned.m16n8k16.row.col.f32.f16.f16.f32 "
        "{%0,%1,%2,%3}, {%4,%5,%6,%7}, {%8,%9}, {%0,%1,%2,%3};"
        : "+f"(c[0]), "+f"(c[1]), "+f"(c[2]), "+f"(c[3])
        : "r"(a[0]), "r"(a[1]), "r"(a[2]), "r"(a[3]), "r"(b0), "r"(b1));
}

__device__ __forceinline__ ull cvt4h(float4 v) {
    __half2 a = __floats2half2_rn(v.x, v.y);
    __half2 b = __floats2half2_rn(v.z, v.w);
    ull r;
    asm("mov.b64 %0, {%1, %2};" : "=l"(r)
        : "r"(*(unsigned*)&a), "r"(*(unsigned*)&b));
    return r;
}

// ===========================================================================
// Reset-mask prep
// ===========================================================================
__global__ void prep_mask_kernel(const void* __restrict__ resets)
{
    const int N = T_ * B_;
    const unsigned char* b8 = (const unsigned char*)resets;
    int found = 0;
    for (int i = threadIdx.x; i < N; i += blockDim.x)
        if ((i & 3) && b8[i] == 1) found = 1;
    int is_byte = __syncthreads_or(found);
    if (is_byte) {
        for (int i = threadIdx.x; i < N; i += blockDim.x)
            g_mask[i] = b8[i] ? 0.0f : 1.0f;
    } else {
        const unsigned int* w32 = (const unsigned int*)resets;
        for (int i = threadIdx.x; i < N; i += blockDim.x)
            g_mask[i] = w32[i] ? 0.0f : 1.0f;
    }
}

// ===========================================================================
// fp16 conversion for A (ins) and B (Wi^T) in ONE kernel
// ===========================================================================
__global__ void conv_ab_kernel(const float* __restrict__ ins,
                               const float* __restrict__ Wi)
{
    const size_t totalA = (size_t)T_ * B_ * D_ / 8;
    const size_t totalB = (size_t)H3_ * (D_ / 8);
    const size_t total = totalA + totalB;
    for (size_t i = (size_t)blockIdx.x * blockDim.x + threadIdx.x;
         i < total; i += (size_t)gridDim.x * blockDim.x) {
        if (i < totalA) {
            size_t base = i * 8;
            float4 a = *(const float4*)(ins + base);
            float4 b = *(const float4*)(ins + base + 4);
            *(ull*)&g_ah[base] = cvt4h(a);
            *(ull*)&g_ah[base + 4] = cvt4h(b);
        } else {
            size_t j = i - totalA;
            int n = (int)(j % H3_);
            int k8 = (int)(j / H3_) * 8;
            float4 a, b;
            a.x = Wi[(size_t)(k8+0)*H3_ + n]; a.y = Wi[(size_t)(k8+1)*H3_ + n];
            a.z = Wi[(size_t)(k8+2)*H3_ + n]; a.w = Wi[(size_t)(k8+3)*H3_ + n];
            b.x = Wi[(size_t)(k8+4)*H3_ + n]; b.y = Wi[(size_t)(k8+5)*H3_ + n];
            b.z = Wi[(size_t)(k8+6)*H3_ + n]; b.w = Wi[(size_t)(k8+7)*H3_ + n];
            size_t o = (size_t)n * D_ + k8;
            *(ull*)&g_bh[o] = cvt4h(a);
            *(ull*)&g_bh[o + 4] = cvt4h(b);
        }
    }
}

// ===========================================================================
// gi GEMM v3: single-pass fp16, 128x128x32, 8 warps, ldmatrix.
// ===========================================================================
#define SAK 40

__global__ __launch_bounds__(256)
void gi_gemm_kernel(const float* __restrict__ bias, float* __restrict__ C)
{
    __shared__ __half sAh[128 * SAK];
    __shared__ __half sBh[128 * SAK];

    const int tid = threadIdx.x;
    const int n0  = blockIdx.x * 128;
    const int m0  = blockIdx.y * 128;
    const int wid = tid >> 5, lane = tid & 31;
    const int wm = (wid & 1) * 64;
    const int wn = (wid >> 1) * 32;
    const int g  = lane >> 2;
    const int tg = lane & 3;

    const int sr = tid >> 1, sk = (tid & 1) * 16;
    const __half* pAh = g_ah + (size_t)(m0 + sr) * D_ + sk;
    const __half* pBh = g_bh + (size_t)(n0 + sr) * D_ + sk;

    const uint32_t aH = smem_u32(sAh) + (((wm + (lane & 15)) * SAK) +
                        ((lane & 16) ? 8 : 0)) * 2;
    const uint32_t bH = smem_u32(sBh) + (((wn + (lane & 7) +
                        ((lane & 16) ? 8 : 0)) * SAK) +
                        ((lane & 8) ? 8 : 0)) * 2;
    const int mstep = 16 * SAK * 2;
    const int nstep = 16 * SAK * 2;

    float acc[4][4][4];
    #pragma unroll
    for (int i = 0; i < 4; i++)
        #pragma unroll
        for (int j = 0; j < 4; j++)
            #pragma unroll
            for (int q = 0; q < 4; q++) acc[i][j][q] = 0.0f;

    uint4 rah0, rah1, rbh0, rbh1;
    rah0 = *(const uint4*)(pAh);     rah1 = *(const uint4*)(pAh + 8);
    rbh0 = *(const uint4*)(pBh);     rbh1 = *(const uint4*)(pBh + 8);

    for (int kc = 0; kc < D_ / 32; kc++) {
        __syncthreads();
        *(uint4*)&sAh[sr * SAK + sk] = rah0;  *(uint4*)&sAh[sr * SAK + sk + 8] = rah1;
        *(uint4*)&sBh[sr * SAK + sk] = rbh0;  *(uint4*)&sBh[sr * SAK + sk + 8] = rbh1;
        __syncthreads();

        if (kc + 1 < D_ / 32) {
            int k0 = (kc + 1) * 32;
            rah0 = *(const uint4*)(pAh + k0);  rah1 = *(const uint4*)(pAh + k0 + 8);
            rbh0 = *(const uint4*)(pBh + k0);  rbh1 = *(const uint4*)(pBh + k0 + 8);
        }

        #pragma unroll
        for (int ks = 0; ks < 2; ks++) {
            const int k2 = ks * 32;
            unsigned bh01[4], bh23[4];
            LDSM4(bh01, bH + k2);
            LDSM4(bh23, bH + nstep + k2);
            #pragma unroll
            for (int mi = 0; mi < 4; mi++) {
                unsigned ah[4];
                LDSM4(ah, aH + mi * mstep + k2);
                mma4(acc[mi][0], ah, bh01[0], bh01[1]);
                mma4(acc[mi][1], ah, bh01[2], bh01[3]);
                mma4(acc[mi][2], ah, bh23[0], bh23[1]);
                mma4(acc[mi][3], ah, bh23[2], bh23[3]);
            }
        }
    }

    #pragma unroll
    for (int ni = 0; ni < 4; ni++) {
        int col = n0 + wn + ni * 8 + tg * 2;
        float b0 = bias[col], b1 = bias[col + 1];
        #pragma unroll
        for (int mi = 0; mi < 4; mi++) {
            int row = m0 + wm + mi * 16 + g;
            float2 o0 = make_float2(acc[mi][ni][0] + b0, acc[mi][ni][1] + b1);
            float2 o1 = make_float2(acc[mi][ni][2] + b0, acc[mi][ni][3] + b1);
            *(float2*)(C + (size_t)row * H3_ + col) = o0;
            *(float2*)(C + (size_t)(row + 8) * H3_ + col) = o1;
        }
    }
}

// ===========================================================================
// Per-batch-group barrier (16 blocks / batch tile)
// ===========================================================================
__device__ __forceinline__ void group_sync(int grp)
{
    __syncthreads();
    if (threadIdx.x == 0) {
        unsigned g = g_gen8[grp * 32];
        __threadfence();
        if (atomicAdd(&g_cnt8[grp * 32], 1) == 15) {
            g_cnt8[grp * 32] = 0;
            __threadfence();
            g_gen8[grp * 32] = g + 1;
        } else {
            while (g_gen8[grp * 32] == g) { __nanosleep(32); }
        }
        __threadfence();
    }
    __syncthreads();
}

// ===========================================================================
// Persistent GRU scan v6: single-pass fp16, 16 warps = 2m x 4n x 2k-split.
// W resident fp16 [96][520] (99.8KB). h chunks of 128k, 4 buffers
// (2 k-halves x 2 chunks). smem k-reduction; 512-thread epilogue.
// ===========================================================================
#define WKS  520
#define HKS  136                         // h chunk row stride (elems)
#define HSBUF 8704                       // bytes per buffer: 32*136*2
#define OFF_HS   99840                   // 96*520*2
#define OFF_GOUT (OFF_HS + 4*HSBUF)      // 134656
#define OFF_GRED (OFF_GOUT + 12800)      // 147456
#define GOUT_STR 100
#define SCAN_SMEM (OFF_GRED + 12800)     // 160256 bytes

__global__ __launch_bounds__(SNTHR, 1)
void gru_scan_kernel(const float* __restrict__ rnn_state,
                     const float* __restrict__ Whrz,
                     const float* __restrict__ Whn,
                     const float* __restrict__ bhn,
                     const float* __restrict__ gi,
                     float* __restrict__ ys)
{
    extern __shared__ char smraw[];
    __half* Whi = (__half*)smraw;
    float* gout = (float*)(smraw + OFF_GOUT);
    float* gred = (float*)(smraw + OFF_GRED);

    const int tid = threadIdx.x;
    const int bid = blockIdx.x;
    const int hti = bid & 15, bti = bid >> 4;
    const int hb  = hti * 32;
    const int b0  = bti * 32;

    const int wid = tid >> 5, lane = tid & 31;
    const int wm  = (wid & 1) * 16;          // m offset
    const int wn  = ((wid >> 1) & 3) * 24;   // n offset
    const int kh  = wid >> 3;                // k half
    const int g   = lane >> 2;
    const int tg  = lane & 3;

    // conversion slot: row = tid>>4 (0..31), k8 = (tid&15)*8
    const int crow = tid >> 4;
    const int ck8  = (tid & 15) * 8;

    // epilogue mapping: float2 per thread over 32b x 32h
    const int eb  = tid >> 4;
    const int eh2 = (tid & 15) * 2;

    const uint32_t smb = smem_u32(smraw);

    // ldmatrix lane bases
    const uint32_t wH01 = smb + (((wn + (lane & 7) + ((lane & 16) ? 8 : 0)) * WKS)
                          + ((lane & 8) ? 8 : 0)) * 2;
    const uint32_t wH2  = smb + (((wn + 16 + (lane & 7)) * WKS)
                          + ((lane & 8) ? 8 : 0)) * 2;
    const uint32_t hLane = (((wm + (lane & 15)) * HKS) + ((lane & 16) ? 8 : 0)) * 2;

    // ---- one-time: W slice -> fp16 resident [96][WKS]
    for (int i = tid; i < 96 * 128; i += SNTHR) {
        int n = i >> 7, kq = (i & 127) * 4;
        int gate = n >> 5, hcol = hb + (n & 31);
        const float* src;
        int stride;
        if (gate == 0)      { src = Whrz + hcol;      stride = H2_; }
        else if (gate == 1) { src = Whrz + H_ + hcol; stride = H2_; }
        else                { src = Whn + hcol;       stride = H_;  }
        float4 v;
        v.x = src[(size_t)(kq + 0) * stride];
        v.y = src[(size_t)(kq + 1) * stride];
        v.z = src[(size_t)(kq + 2) * stride];
        v.w = src[(size_t)(kq + 3) * stride];
        *(ull*)&Whi[n * WKS + kq] = cvt4h(v);
    }

    const float2 bh2 = *(const float2*)(bhn + hb + eh2);
    __syncthreads();

    for (int t = 0; t < T_; t++) {
        const float* hin = (t == 0) ? rnn_state : (ys + (size_t)(t - 1) * B_ * H_);

        const float mc = __ldg(&g_mask[t * B_ + b0 + crow]);
        const float me = __ldg(&g_mask[t * B_ + b0 + eb]);

        // epilogue prefetch
        const float* gib = gi + ((size_t)t * B_ + b0 + eb) * H3_ + hb + eh2;
        float2 ir2 = __ldcg((const float2*)(gib));
        float2 iz2 = __ldcg((const float2*)(gib + H_));
        float2 in2 = __ldcg((const float2*)(gib + 2 * H_));
        float2 ho2 = __ldcg((const float2*)(hin + (size_t)(b0 + eb) * H_ + hb + eh2));

        // h row pointers: half A k[0,256), half B k[256,512)
        const float* hrA = hin + (size_t)(b0 + crow) * H_ + ck8;
        const float* hrB = hrA + 256;

        // prefetch chunk 0 of both halves
        float4 vA0 = __ldcg((const float4*)(hrA));
        float4 vA1 = __ldcg((const float4*)(hrA + 4));
        float4 vB0 = __ldcg((const float4*)(hrB));
        float4 vB1 = __ldcg((const float4*)(hrB + 4));

        float acc[3][4];
        #pragma unroll
        for (int ni = 0; ni < 3; ni++)
            #pragma unroll
            for (int q = 0; q < 4; q++) acc[ni][q] = 0.0f;

        // ---- chunk 0: convert both halves into buf[kh][0]
        {
            __half* bufA = (__half*)(smraw + OFF_HS);            // half0 chunk0
            __half* bufB = (__half*)(smraw + OFF_HS + 2*HSBUF);  // half1 chunk0
            *(ull*)&bufA[crow * HKS + ck8] =
                cvt4h(make_float4(vA0.x*mc, vA0.y*mc, vA0.z*mc, vA0.w*mc));
            *(ull*)&bufA[crow * HKS + ck8 + 4] =
                cvt4h(make_float4(vA1.x*mc, vA1.y*mc, vA1.z*mc, vA1.w*mc));
            *(ull*)&bufB[crow * HKS + ck8] =
                cvt4h(make_float4(vB0.x*mc, vB0.y*mc, vB0.z*mc, vB0.w*mc));
            *(ull*)&bufB[crow * HKS + ck8 + 4] =
                cvt4h(make_float4(vB1.x*mc, vB1.y*mc, vB1.z*mc, vB1.w*mc));
        }
        __syncthreads();

        // prefetch chunk 1
        vA0 = __ldcg((const float4*)(hrA + 128));
        vA1 = __ldcg((const float4*)(hrA + 132));
        vB0 = __ldcg((const float4*)(hrB + 128));
        vB1 = __ldcg((const float4*)(hrB + 132));

        // ---- mma chunk 0
        {
            const uint32_t hA = smb + OFF_HS + (kh * 2) * HSBUF + hLane;
            #pragma unroll
            for (int ks = 0; ks < 8; ks++) {
                const int kw2 = (kh * 256 + ks * 16) * 2;
                const int kl2 = ks * 32;
                unsigned wh01[4], wh2[2], ah[4];
                LDSM4(wh01, wH01 + kw2);
                LDSM2(wh2,  wH2 + kw2);
                LDSM4(ah, hA + kl2);
                mma4(acc[0], ah, wh01[0], wh01[1]);
                mma4(acc[1], ah, wh01[2], wh01[3]);
                mma4(acc[2], ah, wh2[0], wh2[1]);
            }
        }

        // ---- chunk 1: convert both halves into buf[kh][1]
        {
            __half* bufA = (__half*)(smraw + OFF_HS + 1*HSBUF);
            __half* bufB = (__half*)(smraw + OFF_HS + 3*HSBUF);
            *(ull*)&bufA[crow * HKS + ck8] =
                cvt4h(make_float4(vA0.x*mc, vA0.y*mc, vA0.z*mc, vA0.w*mc));
            *(ull*)&bufA[crow * HKS + ck8 + 4] =
                cvt4h(make_float4(vA1.x*mc, vA1.y*mc, vA1.z*mc, vA1.w*mc));
            *(ull*)&bufB[crow * HKS + ck8] =
                cvt4h(make_float4(vB0.x*mc, vB0.y*mc, vB0.z*mc, vB0.w*mc));
            *(ull*)&bufB[crow * HKS + ck8 + 4] =
                cvt4h(make_float4(vB1.x*mc, vB1.y*mc, vB1.z*mc, vB1.w*mc));
        }
        __syncthreads();

        // ---- mma chunk 1
        {
            const uint32_t hA = smb + OFF_HS + (kh * 2 + 1) * HSBUF + hLane;
            #pragma unroll
            for (int ks = 0; ks < 8; ks++) {
                const int kw2 = (kh * 256 + 128 + ks * 16) * 2;
                const int kl2 = ks * 32;
                unsigned wh01[4], wh2[2], ah[4];
                LDSM4(wh01, wH01 + kw2);
                LDSM2(wh2,  wH2 + kw2);
                LDSM4(ah, hA + kl2);
                mma4(acc[0], ah, wh01[0], wh01[1]);
                mma4(acc[1], ah, wh01[2], wh01[3]);
                mma4(acc[2], ah, wh2[0], wh2[1]);
            }
        }

        // ---- k-reduction
        __syncthreads();
        if (kh == 1) {
            #pragma unroll
            for (int ni = 0; ni < 3; ni++) {
                int col = wn + ni * 8 + tg * 2;
                *(float2*)&gred[(wm + g) * GOUT_STR + col] =
                    make_float2(acc[ni][0], acc[ni][1]);
                *(float2*)&gred[(wm + g + 8) * GOUT_STR + col] =
                    make_float2(acc[ni][2], acc[ni][3]);
            }
        }
        __syncthreads();
        if (kh == 0) {
            #pragma unroll
            for (int ni = 0; ni < 3; ni++) {
                int col = wn + ni * 8 + tg * 2;
                float2 p0 = *(const float2*)&gred[(wm + g) * GOUT_STR + col];
                float2 p1 = *(const float2*)&gred[(wm + g + 8) * GOUT_STR + col];
                *(float2*)&gout[(wm + g) * GOUT_STR + col] =
                    make_float2(acc[0 + ni][0] + p0.x, acc[ni][1] + p0.y);
                *(float2*)&gout[(wm + g + 8) * GOUT_STR + col] =
                    make_float2(acc[ni][2] + p1.x, acc[ni][3] + p1.y);
            }
        }
        __syncthreads();

        // ---- fused gates (all 512 threads, float2 each)
        {
            float2 cr = *(const float2*)&gout[eb * GOUT_STR + eh2];
            float2 cz = *(const float2*)&gout[eb * GOUT_STR + 32 + eh2];
            float2 cn = *(const float2*)&gout[eb * GOUT_STR + 64 + eh2];

            float hm0 = ho2.x * me, hm1 = ho2.y * me;
            float r0 = 1.0f / (1.0f + __expf(-(ir2.x + cr.x)));
            float r1 = 1.0f / (1.0f + __expf(-(ir2.y + cr.y)));
            float z0 = 1.0f / (1.0f + __expf(-(iz2.x + cz.x)));
            float z1 = 1.0f / (1.0f + __expf(-(iz2.y + cz.y)));
            float e0 = __expf(2.0f * (in2.x + r0 * (cn.x + bh2.x)));
            float e1 = __expf(2.0f * (in2.y + r1 * (cn.y + bh2.y)));
            float n0 = __fdividef(e0 - 1.0f, e0 + 1.0f);
            float n1 = __fdividef(e1 - 1.0f, e1 + 1.0f);

            float2 out;
            out.x = (1.0f - z0) * n0 + z0 * hm0;
            out.y = (1.0f - z1) * n1 + z1 * hm1;
            *(float2*)(ys + ((size_t)t * B_ + b0 + eb) * H_ + hb + eh2) = out;
        }

        group_sync(bti);
    }
}

// ===========================================================================
extern "C" void kernel_launch(void* const* d_in, const int* in_sizes, int n_in,
                              void* d_out, int out_size)
{
    const float* rnn_state = (const float*)d_in[0];
    const float* ins       = (const float*)d_in[1];
    const void*  resets    = d_in[2];
    const float* Wi        = (const float*)d_in[3];
    const float* bi        = (const float*)d_in[4];
    const float* Whrz      = (const float*)d_in[5];
    const float* Whn       = (const float*)d_in[6];
    const float* bhn       = (const float*)d_in[7];

    float* final_h = (float*)d_out;
    float* ys      = (float*)d_out + (size_t)B_ * H_;

    float* gi_ptr = nullptr;
    cudaGetSymbolAddress((void**)&gi_ptr, g_gi);

    cudaFuncSetAttribute(gru_scan_kernel,
                         cudaFuncAttributeMaxDynamicSharedMemorySize, SCAN_SMEM);

    prep_mask_kernel<<<1, 1024>>>(resets);               // launch #3
    conv_ab_kernel<<<2048, 256>>>(ins, Wi);              // launch #4
    gi_gemm_kernel<<<dim3(H3_ / 128, (T_ * B_) / 128), 256>>>(bi, gi_ptr);  // #5
    gru_scan_kernel<<<NBLK, SNTHR, SCAN_SMEM>>>(rnn_state, Whrz, Whn, bhn,
                                                gi_ptr, ys);                // #6
    cudaMemcpyAsync(final_h, ys + (size_t)(T_ - 1) * B_ * H_,
                    (size_t)B_ * H_ * sizeof(float),
                    cudaMemcpyDeviceToDevice, 0);
}